// round 7
// baseline (speedup 1.0000x reference)
#include <cuda_runtime.h>
#include <math.h>

#define NB 8
#define NC 128
#define NN 20000
#define TN 128
#define NT 157
#define SROW 132
#define NTH 512
#define EPSV 1e-5f
#define INVTEMP 0.08838834764831845f  // 1/sqrt(128)

__device__ float g_v[(size_t)NB * NC * NN];      // ~82 MB, layout [b][d][n]
__device__ float g_attn[(size_t)NB * NC * NC];   // 512 KB
__device__ float g_par[11 * NC];

// proj_attn smem float offsets
#define OFF_PC 0          // pc [128][132]
#define OFF_QS 16896      // qs [128][132]
#define OFF_KG 33792      // kg [128][132] (rot-swizzled rows)
#define OFF_WS 50688      // ws [16][132] plain
#define OFF_PAR 52800     // 11*128
#define OFF_X  54208      // [4][128]
#define SMEM_A_FLOATS 54720
#define SMEM_A_BYTES (SMEM_A_FLOATS * 4)   // 218880 B

// out_kernel smem
#define OFF_AS 0          // a [128][132] plain
#define OFF_VS 16896      // v [128][132]
#define SMEM_O_FLOATS 33792
#define SMEM_O_BYTES (SMEM_O_FLOATS * 4)   // 135168 B

typedef unsigned long long u64;
typedef unsigned int u32;

__device__ __forceinline__ u64 pk2(float lo, float hi) {
    u64 r; asm("mov.b64 %0,{%1,%2};" : "=l"(r) : "f"(lo), "f"(hi)); return r;
}
__device__ __forceinline__ u64 dup2(float f) {
    u64 r; asm("mov.b64 %0,{%1,%1};" : "=l"(r) : "f"(f)); return r;
}
__device__ __forceinline__ float2 upk2(u64 v) {
    float2 r; asm("mov.b64 {%0,%1},%2;" : "=f"(r.x), "=f"(r.y) : "l"(v)); return r;
}
__device__ __forceinline__ void fma2(u64& d, u64 a, u64 b) {
    asm("fma.rn.f32x2 %0,%1,%2,%0;" : "+l"(d) : "l"(a), "l"(b));
}
__device__ __forceinline__ u64 lds64(u32 a) {
    u64 r; asm volatile("ld.shared.b64 %0,[%1];" : "=l"(r) : "r"(a)); return r;
}
__device__ __forceinline__ void lds128(u64& x, u64& y, u32 a) {
    asm volatile("ld.shared.v2.u64 {%0,%1},[%2];" : "=l"(x), "=l"(y) : "r"(a));
}
__device__ __forceinline__ void sts64(u32 a, u64 v) {
    asm volatile("st.shared.b64 [%0],%1;" :: "r"(a), "l"(v));
}
__device__ __forceinline__ u32 smem_u32(const void* p) {
    u32 a;
    asm("{.reg .u64 t; cvta.to.shared.u64 t,%1; cvt.u32.u64 %0,t;}" : "=r"(a) : "l"(p));
    return a;
}

// ---- one-time parameter folding ----
__global__ void prep_kernel(const float* __restrict__ gq, const float* __restrict__ bq,
                            const float* __restrict__ mq, const float* __restrict__ vq,
                            const float* __restrict__ gk, const float* __restrict__ bk,
                            const float* __restrict__ mk, const float* __restrict__ vk,
                            const float* __restrict__ gv, const float* __restrict__ bv,
                            const float* __restrict__ mv, const float* __restrict__ vv,
                            const float* __restrict__ Wg1, const float* __restrict__ bg1,
                            const float* __restrict__ Wg2, const float* __restrict__ bg2)
{
    int o = threadIdx.x;
    float s;
    s = gq[o] * rsqrtf(vq[o] + EPSV); g_par[o]       = s; g_par[128 + o] = bq[o] - mq[o] * s;
    s = gk[o] * rsqrtf(vk[o] + EPSV); g_par[256 + o] = s; g_par[384 + o] = bk[o] - mk[o] * s;
    s = gv[o] * rsqrtf(vv[o] + EPSV); g_par[512 + o] = s; g_par[640 + o] = bv[o] - mv[o] * s;
    g_par[768 + o]  = Wg1[o * 2];
    g_par[896 + o]  = Wg1[o * 2 + 1];
    g_par[1024 + o] = Wg2[o * 2];
    g_par[1152 + o] = Wg2[o * 2 + 1];
    g_par[1280 + o] = bg1[o] + bg2[o];
    for (int idx = threadIdx.x; idx < NB * NC * NC; idx += blockDim.x)
        g_attn[idx] = 0.f;
}

// packed 128x128x128 GEMM. out rows o=4*ty+i (i<4), cols n = 4*tx + 64*(j>>1) + 2*(j&1).
__device__ __forceinline__ void gemm_f2(const float* __restrict__ Wp,
                                        float* sm, u32 sPC,
                                        int tx, int ty, int tid, u64 acc[4][4])
{
#pragma unroll
    for (int i = 0; i < 4; i++)
#pragma unroll
        for (int j = 0; j < 4; j++) acc[i][j] = 0ull;

    for (int kk = 0; kk < 8; kk++) {
        __syncthreads();   // protect ws from previous consumers
        // stage W[o][kk*16+cc] -> ws[cc][o], plain floats; 512 threads cover it
        {
            int o = tid >> 2, cq = tid & 3;
            float4 w = *(const float4*)(Wp + o * NC + kk * 16 + cq * 4);
            float* wsb = sm + OFF_WS + cq * 4 * SROW + o;
            wsb[0]        = w.x;
            wsb[SROW]     = w.y;
            wsb[2 * SROW] = w.z;
            wsb[3 * SROW] = w.w;
        }
        __syncthreads();
#pragma unroll 4
        for (int cc = 0; cc < 16; cc++) {
            // 4 w values for this thread: 1 x LDS.128 (broadcast across tx)
            float4 wa = *(const float4*)(sm + OFF_WS + cc * SROW + 4 * ty);
            u64 a2[4];
            a2[0] = dup2(wa.x); a2[1] = dup2(wa.y); a2[2] = dup2(wa.z); a2[3] = dup2(wa.w);
            u64 b2[4];
            u32 pb = sPC + (u32)((kk * 16 + cc) * SROW + 4 * tx) * 4;
            lds128(b2[0], b2[1], pb);
            lds128(b2[2], b2[3], pb + 64 * 4);
#pragma unroll
            for (int i = 0; i < 4; i++)
#pragma unroll
                for (int j = 0; j < 4; j++)
                    fma2(acc[i][j], a2[i], b2[j]);
        }
    }
}

__global__ __launch_bounds__(NTH, 1)
void proj_attn_kernel(const float* __restrict__ pc, const float* __restrict__ xin,
                      const float* __restrict__ Wq, const float* __restrict__ Wk,
                      const float* __restrict__ Wv)
{
    extern __shared__ float sm[];
    float* par = sm + OFF_PAR;
    float* x_s = sm + OFF_X;
    const u32 sbase = smem_u32(sm);
    const u32 sPC = sbase + OFF_PC * 4;
    const u32 sQS = sbase + OFF_QS * 4;
    const u32 sKG = sbase + OFF_KG * 4;
    const u32 sX  = sbase + OFF_X * 4;

    const int tid = threadIdx.x;
    const int tx = tid & 15;
    const int ty = tid >> 4;          // 0..31
    const int tile = blockIdx.x;
    const int b = blockIdx.y;
    const int n0 = tile * TN;
    const bool fullt = (n0 + TN <= NN);

    for (int idx = tid; idx < 11 * NC; idx += NTH)
        par[idx] = g_par[idx];

    if (fullt) {
        for (int idx = tid; idx < NC * (TN / 4); idx += NTH) {
            int c = idx >> 5, q = idx & 31;
            float4 val = *(const float4*)(pc + ((size_t)b * NC + c) * NN + n0 + q * 4);
            *(float4*)(sm + OFF_PC + c * SROW + q * 4) = val;
        }
    } else {
        for (int idx = tid; idx < NC * TN; idx += NTH) {
            int c = idx >> 7, nn = idx & 127;
            int n = n0 + nn;
            sm[OFF_PC + c * SROW + nn] = (n < NN) ? pc[((size_t)b * NC + c) * NN + n] : 0.f;
        }
    }
    for (int idx = tid; idx < 4 * TN; idx += NTH) {
        int ch = idx >> 7, nn = idx & 127;
        int n = n0 + nn;
        x_s[ch * 128 + nn] = (n < NN) ? xin[((size_t)b * 4 + ch) * NN + n] : 0.f;
    }
    // gemm_f2's first __syncthreads orders fills before use

    u64 acc[4][4];

    // ---- q projection -> qs (BN + relu + /temp) ----
    gemm_f2(Wq, sm, sPC, tx, ty, tid, acc);
#pragma unroll
    for (int i = 0; i < 4; i++) {
        int o = 4 * ty + i;
        float sc = par[o], sh = par[128 + o];
#pragma unroll
        for (int j = 0; j < 4; j++) {
            int nb = 4 * tx + 64 * (j >> 1) + 2 * (j & 1);
            float2 p = upk2(acc[i][j]);
            float v0 = fmaxf(fmaf(p.x, sc, sh), 0.f) * INVTEMP;
            float v1 = fmaxf(fmaf(p.y, sc, sh), 0.f) * INVTEMP;
            if (!fullt) {
                if (n0 + nb >= NN) v0 = 0.f;
                if (n0 + nb + 1 >= NN) v1 = 0.f;
            }
            sts64(sQS + (u32)(o * SROW + nb) * 4, pk2(v0, v1));
        }
    }

    // ---- k projection + graph context -> kg (rot-swizzled rows) ----
    gemm_f2(Wk, sm, sPC, tx, ty, tid, acc);
    {
        u64 xp[4][4];
#pragma unroll
        for (int j = 0; j < 4; j++) {
            int nb = 4 * tx + 64 * (j >> 1) + 2 * (j & 1);
#pragma unroll
            for (int ch = 0; ch < 4; ch++)
                xp[ch][j] = lds64(sX + (u32)(ch * 128 + nb) * 4);
        }
#pragma unroll
        for (int i = 0; i < 4; i++) {
            int o = 4 * ty + i;
            float sc = par[256 + o], sh = par[384 + o];
            u64 w0 = dup2(par[768 + o]);
            u64 w1 = dup2(par[896 + o]);
            u64 w2 = dup2(par[1024 + o]);
            u64 w3 = dup2(par[1152 + o]);
            float bgg = par[1280 + o];
            int rot = 4 * (o & 31);
#pragma unroll
            for (int j = 0; j < 4; j++) {
                int nb = 4 * tx + 64 * (j >> 1) + 2 * (j & 1);
                u64 g2 = dup2(bgg);
                fma2(g2, w0, xp[0][j]);
                fma2(g2, w1, xp[1][j]);
                fma2(g2, w2, xp[2][j]);
                fma2(g2, w3, xp[3][j]);
                float2 gc = upk2(g2);
                float2 p = upk2(acc[i][j]);
                float v0 = fmaxf(fmaf(p.x, sc, sh), 0.f) + gc.x;
                float v1 = fmaxf(fmaf(p.y, sc, sh), 0.f) + gc.y;
                if (!fullt) {
                    if (n0 + nb >= NN) v0 = 0.f;
                    if (n0 + nb + 1 >= NN) v1 = 0.f;
                }
                int phys = (nb + rot) & 127;
                sts64(sKG + (u32)(o * SROW + phys) * 4, pk2(v0, v1));
            }
        }
    }

    // ---- v projection -> g_v[b][d][n] ----
    gemm_f2(Wv, sm, sPC, tx, ty, tid, acc);
#pragma unroll
    for (int i = 0; i < 4; i++) {
        int o = 4 * ty + i;
        float sc = par[512 + o], sh = par[640 + o];
#pragma unroll
        for (int j4 = 0; j4 < 2; j4++) {
            float2 pa = upk2(acc[i][2 * j4]);
            float2 pb = upk2(acc[i][2 * j4 + 1]);
            float4 v;
            v.x = fmaxf(fmaf(pa.x, sc, sh), 0.f);
            v.y = fmaxf(fmaf(pa.y, sc, sh), 0.f);
            v.z = fmaxf(fmaf(pb.x, sc, sh), 0.f);
            v.w = fmaxf(fmaf(pb.y, sc, sh), 0.f);
            int nb = 4 * tx + 64 * j4;
            size_t gaddr = ((size_t)b * NC + o) * NN + n0 + nb;
            if (fullt) {
                *(float4*)(g_v + gaddr) = v;
            } else {
                if (n0 + nb < NN)     g_v[gaddr]     = v.x;
                if (n0 + nb + 1 < NN) g_v[gaddr + 1] = v.y;
                if (n0 + nb + 2 < NN) g_v[gaddr + 2] = v.z;
                if (n0 + nb + 3 < NN) g_v[gaddr + 3] = v.w;
            }
        }
    }

    // ---- attn partial: reduction-packed over n ----
    __syncthreads();
    u64 at[4][8];
#pragma unroll
    for (int i = 0; i < 4; i++)
#pragma unroll
        for (int j = 0; j < 8; j++) at[i][j] = 0ull;

    for (int nq = 0; nq < 32; nq++) {
        u64 qa[4][2];
#pragma unroll
        for (int i = 0; i < 4; i++)
            lds128(qa[i][0], qa[i][1], sQS + (u32)((4 * ty + i) * SROW + 4 * nq) * 4);
#pragma unroll
        for (int h = 0; h < 2; h++) {
            u64 kb[4][2];
#pragma unroll
            for (int jj = 0; jj < 4; jj++) {
                int j = h * 4 + jj;
                int d = tx + 16 * j;
                int phys = (4 * nq + 4 * (d & 31)) & 127;
                lds128(kb[jj][0], kb[jj][1], sKG + (u32)(d * SROW + phys) * 4);
            }
#pragma unroll
            for (int i = 0; i < 4; i++)
#pragma unroll
                for (int jj = 0; jj < 4; jj++) {
                    fma2(at[i][h * 4 + jj], qa[i][0], kb[jj][0]);
                    fma2(at[i][h * 4 + jj], qa[i][1], kb[jj][1]);
                }
        }
    }

#pragma unroll
    for (int i = 0; i < 4; i++) {
        int c = 4 * ty + i;
#pragma unroll
        for (int j = 0; j < 8; j++) {
            int d = tx + 16 * j;
            float2 s = upk2(at[i][j]);
            atomicAdd(&g_attn[((size_t)b * NC + c) * NC + d], s.x + s.y);
        }
    }
}

__global__ void softmax_kernel()
{
    __shared__ float red[NC];
    const int row = blockIdx.x;
    const int t = threadIdx.x;
    float* a = g_attn + (size_t)row * NC;
    float v = a[t];
    red[t] = v;
    __syncthreads();
    for (int s = 64; s > 0; s >>= 1) {
        if (t < s) red[t] = fmaxf(red[t], red[t + s]);
        __syncthreads();
    }
    float mx = red[0];
    __syncthreads();
    float e = expf(v - mx);
    red[t] = e;
    __syncthreads();
    for (int s = 64; s > 0; s >>= 1) {
        if (t < s) red[t] += red[t + s];
        __syncthreads();
    }
    float inv = 1.f / red[0];
    a[t] = e * inv;
}

__global__ __launch_bounds__(NTH, 1)
void out_kernel(float* __restrict__ out)
{
    extern __shared__ float sm[];
    const u32 sbase = smem_u32(sm);
    const u32 sVS = sbase + OFF_VS * 4;

    const int tid = threadIdx.x;
    const int tx = tid & 15;
    const int ty = tid >> 4;          // 0..31
    const int tile = blockIdx.x;
    const int b = blockIdx.y;
    const int n0 = tile * TN;
    const bool fullt = (n0 + TN <= NN);

    // plain a[c][d] (stride 132)
    for (int idx = tid; idx < NC * NC; idx += NTH) {
        int c = idx >> 7, d = idx & 127;
        sm[OFF_AS + c * SROW + d] = g_attn[(size_t)b * NC * NC + idx];
    }
    if (fullt) {
        for (int idx = tid; idx < NC * (TN / 4); idx += NTH) {
            int d = idx >> 5, q = idx & 31;
            float4 val = *(const float4*)(g_v + ((size_t)b * NC + d) * NN + n0 + q * 4);
            *(float4*)(sm + OFF_VS + d * SROW + q * 4) = val;
        }
    } else {
        for (int idx = tid; idx < NC * TN; idx += NTH) {
            int d = idx >> 7, nn = idx & 127;
            int n = n0 + nn;
            sm[OFF_VS + d * SROW + nn] = (n < NN) ? g_v[((size_t)b * NC + d) * NN + n] : 0.f;
        }
    }
    __syncthreads();

    u64 oacc[4][4];
#pragma unroll
    for (int i = 0; i < 4; i++)
#pragma unroll
        for (int j = 0; j < 4; j++) oacc[i][j] = 0ull;

    for (int dq = 0; dq < 64; dq++) {
        float2 av[4];
#pragma unroll
        for (int i = 0; i < 4; i++)
            av[i] = *(const float2*)(sm + OFF_AS + (4 * ty + i) * SROW + 2 * dq);
        u64 vb[2][2][2];
#pragma unroll
        for (int dd = 0; dd < 2; dd++)
#pragma unroll
            for (int j4 = 0; j4 < 2; j4++)
                lds128(vb[dd][j4][0], vb[dd][j4][1],
                       sVS + (u32)((2 * dq + dd) * SROW + 4 * tx + 64 * j4) * 4);
#pragma unroll
        for (int i = 0; i < 4; i++) {
            u64 a0 = dup2(av[i].x);
            u64 a1 = dup2(av[i].y);
#pragma unroll
            for (int j = 0; j < 4; j++) {
                fma2(oacc[i][j], a0, vb[0][j >> 1][j & 1]);
                fma2(oacc[i][j], a1, vb[1][j >> 1][j & 1]);
            }
        }
    }

#pragma unroll
    for (int i = 0; i < 4; i++) {
        int c = 4 * ty + i;
#pragma unroll
        for (int j4 = 0; j4 < 2; j4++) {
            float2 pa = upk2(oacc[i][2 * j4]);
            float2 pb = upk2(oacc[i][2 * j4 + 1]);
            int nb = 4 * tx + 64 * j4;
            size_t gaddr = ((size_t)b * NC + c) * NN + n0 + nb;
            if (fullt) {
                float4 v; v.x = pa.x; v.y = pa.y; v.z = pb.x; v.w = pb.y;
                *(float4*)(out + gaddr) = v;
            } else {
                if (n0 + nb < NN)     out[gaddr]     = pa.x;
                if (n0 + nb + 1 < NN) out[gaddr + 1] = pa.y;
                if (n0 + nb + 2 < NN) out[gaddr + 2] = pb.x;
                if (n0 + nb + 3 < NN) out[gaddr + 3] = pb.y;
            }
        }
    }
}

extern "C" void kernel_launch(void* const* d_in, const int* in_sizes, int n_in,
                              void* d_out, int out_size)
{
    const float* pc  = (const float*)d_in[0];
    const float* x   = (const float*)d_in[1];
    const float* Wq  = (const float*)d_in[2];
    const float* gq  = (const float*)d_in[3];
    const float* bq  = (const float*)d_in[4];
    const float* mq  = (const float*)d_in[5];
    const float* vq  = (const float*)d_in[6];
    const float* Wk  = (const float*)d_in[7];
    const float* gk  = (const float*)d_in[8];
    const float* bk  = (const float*)d_in[9];
    const float* mk  = (const float*)d_in[10];
    const float* vk  = (const float*)d_in[11];
    const float* Wv  = (const float*)d_in[12];
    const float* gv  = (const float*)d_in[13];
    const float* bv  = (const float*)d_in[14];
    const float* mv  = (const float*)d_in[15];
    const float* vv  = (const float*)d_in[16];
    const float* Wg1 = (const float*)d_in[17];
    const float* bg1 = (const float*)d_in[18];
    const float* Wg2 = (const float*)d_in[19];
    const float* bg2 = (const float*)d_in[20];
    float* out = (float*)d_out;

    cudaFuncSetAttribute(proj_attn_kernel,
                         cudaFuncAttributeMaxDynamicSharedMemorySize, SMEM_A_BYTES);
    cudaFuncSetAttribute(out_kernel,
                         cudaFuncAttributeMaxDynamicSharedMemorySize, SMEM_O_BYTES);

    prep_kernel<<<1, NC>>>(gq, bq, mq, vq, gk, bk, mk, vk, gv, bv, mv, vv,
                           Wg1, bg1, Wg2, bg2);

    dim3 grid(NT, NB);
    proj_attn_kernel<<<grid, NTH, SMEM_A_BYTES>>>(pc, x, Wq, Wk, Wv);
    softmax_kernel<<<NB * NC, NC>>>();
    out_kernel<<<grid, NTH, SMEM_O_BYTES>>>(out);
}

// round 9
// speedup vs baseline: 1.1558x; 1.1558x over previous
#include <cuda_runtime.h>
#include <cuda_bf16.h>
#include <mma.h>
#include <math.h>
using namespace nvcuda;

#define NB 8
#define NC 128
#define NN 20000
#define TN 128
#define NT 157
#define NTH 512
#define LDT 136              // bf16 tile leading dim (elements, %8==0 for wmma)
#define LDTB 272             // bytes per tile row
#define EPSV 1e-5f
#define INVTEMP 0.08838834764831845f  // 1/sqrt(128)

typedef unsigned int u32;

// scratch (__device__ statics: allocation-free per harness rules)
__device__ float g_v[(size_t)NB * NT * TN * NC];   // [b][tile][n][d], ~82 MB
__device__ float g_attn[(size_t)NB * NC * NC];
__device__ float g_par[11 * NC];
__device__ __nv_bfloat16 g_Wb[3][2][NC * NC];      // plain [o][c] bf16 hi/lo

// ---- proj kernel smem byte offsets ----
#define PB_HI 0            // pc^T / later kg : [row][k] 128x136 bf16
#define PB_LO 34816
#define PW_HI 69632        // W : [o][c]
#define PW_LO 104448
#define PQ_HI 139264       // qs : [c][n]
#define PQ_LO 174080
#define PSTG  208896       // 16 warps x 1280 B fp32 stage (16x20)
#define PX    229376       // x tile: 512 floats
#define SMEM_A_BYTES 231424

// ---- out kernel smem byte offsets ----
#define OA_HI 0            // attn [c][d]
#define OA_LO 34816
#define OB_HI 69632        // v [n][d]
#define OB_LO 104448
#define OSTG  139264
#define SMEM_O_BYTES 159744

typedef wmma::fragment<wmma::matrix_a, 16, 16, 16, __nv_bfloat16, wmma::row_major> FragA;
typedef wmma::fragment<wmma::matrix_b, 16, 16, 16, __nv_bfloat16, wmma::col_major> FragB;
typedef wmma::fragment<wmma::accumulator, 16, 16, 16, float> FragC;

__device__ __forceinline__ u32 split_pair(float a, float b, u32& lo_pair) {
    __nv_bfloat16 ha = __float2bfloat16(a);
    __nv_bfloat16 hb = __float2bfloat16(b);
    __nv_bfloat16 la = __float2bfloat16(a - __bfloat162float(ha));
    __nv_bfloat16 lb = __float2bfloat16(b - __bfloat162float(hb));
    lo_pair = (u32)__bfloat16_as_ushort(la) | ((u32)__bfloat16_as_ushort(lb) << 16);
    return (u32)__bfloat16_as_ushort(ha) | ((u32)__bfloat16_as_ushort(hb) << 16);
}

// warp 32x32 tile of a 128x128x128 GEMM, bf16 two-term split (hh + hl + lh)
__device__ __forceinline__ void gemm_tile(const __nv_bfloat16* Ah, const __nv_bfloat16* Al,
                                          const __nv_bfloat16* Bh, const __nv_bfloat16* Bl,
                                          int wm, int wn, FragC acc[2][2])
{
#pragma unroll
    for (int i = 0; i < 2; i++)
#pragma unroll
        for (int j = 0; j < 2; j++) wmma::fill_fragment(acc[i][j], 0.f);

#pragma unroll
    for (int k = 0; k < 8; k++) {
        FragA ah[2], al[2];
        FragB bh[2], bl[2];
#pragma unroll
        for (int i = 0; i < 2; i++) {
            wmma::load_matrix_sync(ah[i], Ah + (wm + 16 * i) * LDT + 16 * k, LDT);
            wmma::load_matrix_sync(al[i], Al + (wm + 16 * i) * LDT + 16 * k, LDT);
        }
#pragma unroll
        for (int j = 0; j < 2; j++) {
            wmma::load_matrix_sync(bh[j], Bh + (wn + 16 * j) * LDT + 16 * k, LDT);
            wmma::load_matrix_sync(bl[j], Bl + (wn + 16 * j) * LDT + 16 * k, LDT);
        }
#pragma unroll
        for (int i = 0; i < 2; i++)
#pragma unroll
            for (int j = 0; j < 2; j++) {
                wmma::mma_sync(acc[i][j], ah[i], bh[j], acc[i][j]);
                wmma::mma_sync(acc[i][j], ah[i], bl[j], acc[i][j]);
                wmma::mma_sync(acc[i][j], al[i], bh[j], acc[i][j]);
            }
    }
}

// stage one 16x16 acc frag through warp-private smem; v[t] = element (lane>>1, (lane&1)*8 + t)
__device__ __forceinline__ void frag_vals(float* ws, const FragC& f, int lane, float* v)
{
    wmma::store_matrix_sync(ws, f, 20, wmma::mem_row_major);
    __syncwarp();
    const float* p = ws + (lane >> 1) * 20 + (lane & 1) * 8;
    float4 a = *(const float4*)p;
    float4 b = *(const float4*)(p + 4);
    v[0] = a.x; v[1] = a.y; v[2] = a.z; v[3] = a.w;
    v[4] = b.x; v[5] = b.y; v[6] = b.z; v[7] = b.w;
    __syncwarp();
}

// ---- one-time prep ----
__global__ void prep_kernel(const float* __restrict__ Wq, const float* __restrict__ Wk,
                            const float* __restrict__ Wv,
                            const float* __restrict__ gq, const float* __restrict__ bq,
                            const float* __restrict__ mq, const float* __restrict__ vq,
                            const float* __restrict__ gk, const float* __restrict__ bk,
                            const float* __restrict__ mk, const float* __restrict__ vk,
                            const float* __restrict__ gv, const float* __restrict__ bv,
                            const float* __restrict__ mv, const float* __restrict__ vv,
                            const float* __restrict__ Wg1, const float* __restrict__ bg1,
                            const float* __restrict__ Wg2, const float* __restrict__ bg2)
{
    int t = threadIdx.x;
    if (t < NC) {
        int o = t;
        float s;
        s = gq[o] * rsqrtf(vq[o] + EPSV); g_par[o]       = s; g_par[128 + o] = bq[o] - mq[o] * s;
        s = gk[o] * rsqrtf(vk[o] + EPSV); g_par[256 + o] = s; g_par[384 + o] = bk[o] - mk[o] * s;
        s = gv[o] * rsqrtf(vv[o] + EPSV); g_par[512 + o] = s; g_par[640 + o] = bv[o] - mv[o] * s;
        g_par[768 + o]  = Wg1[o * 2];
        g_par[896 + o]  = Wg1[o * 2 + 1];
        g_par[1024 + o] = Wg2[o * 2];
        g_par[1152 + o] = Wg2[o * 2 + 1];
        g_par[1280 + o] = bg1[o] + bg2[o];
    }
    for (int idx = t; idx < NB * NC * NC; idx += blockDim.x)
        g_attn[idx] = 0.f;
    for (int idx = t; idx < 3 * NC * NC; idx += blockDim.x) {
        int m = idx >> 14, e = idx & 16383;
        const float* Wp = (m == 0) ? Wq : (m == 1) ? Wk : Wv;
        float w = Wp[e];
        __nv_bfloat16 hi = __float2bfloat16(w);
        __nv_bfloat16 lo = __float2bfloat16(w - __bfloat162float(hi));
        g_Wb[m][0][e] = hi;
        g_Wb[m][1][e] = lo;
    }
}

// stage W matrix m (bf16 hi/lo, plain [o][c]) into smem tiles (ldm 136)
__device__ __forceinline__ void stage_W(char* smem, int m, int tid) {
    const u32* srcH = (const u32*)g_Wb[m][0];
    const u32* srcL = (const u32*)g_Wb[m][1];
#pragma unroll
    for (int k = 0; k < 16; k++) {
        int idx = tid + k * NTH;           // 8192 u32 per half
        int row = idx >> 6, cq = idx & 63;
        *(u32*)(smem + PW_HI + row * LDTB + cq * 4) = srcH[idx];
        *(u32*)(smem + PW_LO + row * LDTB + cq * 4) = srcL[idx];
    }
}

__global__ __launch_bounds__(NTH, 1)
void proj_attn_kernel(const float* __restrict__ pc, const float* __restrict__ xin)
{
    extern __shared__ char smem[];
    const int tid = threadIdx.x;
    const int w = tid >> 5;
    const int lane = tid & 31;
    const int wm = (w & 3) * 32;      // output-row tile
    const int wn = (w >> 2) * 32;     // output-col tile
    const int tile = blockIdx.x;
    const int b = blockIdx.y;
    const int n0 = tile * TN;

    float* xs = (float*)(smem + PX);
    float* ws = (float*)(smem + PSTG) + w * 320;   // 16x20 fp32 warp stage

    const __nv_bfloat16* B_HIp = (const __nv_bfloat16*)(smem + PB_HI);
    const __nv_bfloat16* B_LOp = (const __nv_bfloat16*)(smem + PB_LO);
    const __nv_bfloat16* W_HIp = (const __nv_bfloat16*)(smem + PW_HI);
    const __nv_bfloat16* W_LOp = (const __nv_bfloat16*)(smem + PW_LO);
    const __nv_bfloat16* Q_HIp = (const __nv_bfloat16*)(smem + PQ_HI);
    const __nv_bfloat16* Q_LOp = (const __nv_bfloat16*)(smem + PQ_LO);

    // fill pc^T tile [n][c] bf16 hi/lo
    for (int idx = tid; idx < 64 * TN; idx += NTH) {
        int n = idx & 127, cp = idx >> 7;   // c = 2*cp
        int c = 2 * cp;
        int gn = n0 + n;
        float v0 = 0.f, v1 = 0.f;
        if (gn < NN) {
            v0 = pc[((size_t)b * NC + c) * NN + gn];
            v1 = pc[((size_t)b * NC + c + 1) * NN + gn];
        }
        u32 lop, hip = split_pair(v0, v1, lop);
        *(u32*)(smem + PB_HI + n * LDTB + 2 * c) = hip;
        *(u32*)(smem + PB_LO + n * LDTB + 2 * c) = lop;
    }
    for (int idx = tid; idx < 4 * TN; idx += NTH) {
        int ch = idx >> 7, nn = idx & 127;
        int n = n0 + nn;
        xs[ch * 128 + nn] = (n < NN) ? xin[((size_t)b * 4 + ch) * NN + n] : 0.f;
    }
    stage_W(smem, 0, tid);   // Wq
    __syncthreads();

    FragC acc[2][2];
    float vals[8];

    // ---- q GEMM: W[o][c] x pc[c][n] -> qs[o][n] ----
    gemm_tile(W_HIp, W_LOp, B_HIp, B_LOp, wm, wn, acc);
#pragma unroll
    for (int i = 0; i < 2; i++) {
        int o = wm + 16 * i + (lane >> 1);
        float sc = g_par[o], sh = g_par[128 + o];
#pragma unroll
        for (int j = 0; j < 2; j++) {
            frag_vals(ws, acc[i][j], lane, vals);
            int nb = wn + 16 * j + (lane & 1) * 8;
#pragma unroll
            for (int tp = 0; tp < 4; tp++) {
                int n = nb + 2 * tp;
                float v0 = fmaxf(fmaf(vals[2 * tp], sc, sh), 0.f) * INVTEMP;
                float v1 = fmaxf(fmaf(vals[2 * tp + 1], sc, sh), 0.f) * INVTEMP;
                if (n0 + n >= NN) v0 = 0.f;
                if (n0 + n + 1 >= NN) v1 = 0.f;
                u32 lop, hip = split_pair(v0, v1, lop);
                *(u32*)(smem + PQ_HI + o * LDTB + 2 * n) = hip;
                *(u32*)(smem + PQ_LO + o * LDTB + 2 * n) = lop;
            }
        }
    }
    __syncthreads();
    stage_W(smem, 2, tid);   // Wv
    __syncthreads();

    // ---- v GEMM -> g_v[b][tile][n][d] ----
    gemm_tile(W_HIp, W_LOp, B_HIp, B_LOp, wm, wn, acc);
    {
        float* gvt = g_v + (size_t)(b * NT + tile) * (TN * NC);
#pragma unroll
        for (int i = 0; i < 2; i++) {
            int d = wm + 16 * i + (lane >> 1);
            float sc = g_par[512 + d], sh = g_par[640 + d];
#pragma unroll
            for (int j = 0; j < 2; j++) {
                frag_vals(ws, acc[i][j], lane, vals);
                int nb = wn + 16 * j + (lane & 1) * 8;
#pragma unroll
                for (int t = 0; t < 8; t++)
                    gvt[(size_t)(nb + t) * NC + d] = fmaxf(fmaf(vals[t], sc, sh), 0.f);
            }
        }
    }
    __syncthreads();
    stage_W(smem, 1, tid);   // Wk
    __syncthreads();

    // ---- k GEMM ----
    gemm_tile(W_HIp, W_LOp, B_HIp, B_LOp, wm, wn, acc);
    __syncthreads();   // everyone done reading pc tile before kg overwrites it
#pragma unroll
    for (int i = 0; i < 2; i++) {
        int o = wm + 16 * i + (lane >> 1);
        float sc = g_par[256 + o], sh = g_par[384 + o];
        float w10 = g_par[768 + o], w11 = g_par[896 + o];
        float w20 = g_par[1024 + o], w21 = g_par[1152 + o];
        float bgg = g_par[1280 + o];
#pragma unroll
        for (int j = 0; j < 2; j++) {
            frag_vals(ws, acc[i][j], lane, vals);
            int nb = wn + 16 * j + (lane & 1) * 8;
#pragma unroll
            for (int tp = 0; tp < 4; tp++) {
                int n = nb + 2 * tp;
                float gc0 = fmaf(w10, xs[n],     fmaf(w11, xs[128 + n],     fmaf(w20, xs[256 + n],     fmaf(w21, xs[384 + n],     bgg))));
                float gc1 = fmaf(w10, xs[n + 1], fmaf(w11, xs[128 + n + 1], fmaf(w20, xs[256 + n + 1], fmaf(w21, xs[384 + n + 1], bgg))));
                float v0 = fmaxf(fmaf(vals[2 * tp], sc, sh), 0.f) + gc0;
                float v1 = fmaxf(fmaf(vals[2 * tp + 1], sc, sh), 0.f) + gc1;
                if (n0 + n >= NN) v0 = 0.f;
                if (n0 + n + 1 >= NN) v1 = 0.f;
                u32 lop, hip = split_pair(v0, v1, lop);
                *(u32*)(smem + PB_HI + o * LDTB + 2 * n) = hip;   // kg reuses pc region
                *(u32*)(smem + PB_LO + o * LDTB + 2 * n) = lop;
            }
        }
    }
    __syncthreads();

    // ---- attn partial: qs[c][n] x kg[d][n]^T ----
    gemm_tile(Q_HIp, Q_LOp, B_HIp, B_LOp, wm, wn, acc);
#pragma unroll
    for (int i = 0; i < 2; i++) {
        int c = wm + 16 * i + (lane >> 1);
        float* dst = g_attn + ((size_t)b * NC + c) * NC;
#pragma unroll
        for (int j = 0; j < 2; j++) {
            frag_vals(ws, acc[i][j], lane, vals);
            int db = wn + 16 * j + (lane & 1) * 8;
#pragma unroll
            for (int t = 0; t < 8; t++)
                atomicAdd(dst + db + t, vals[t]);
        }
    }
}

__global__ void softmax_kernel()
{
    __shared__ float red[NC];
    const int row = blockIdx.x;
    const int t = threadIdx.x;
    float* a = g_attn + (size_t)row * NC;
    float v = a[t];
    red[t] = v;
    __syncthreads();
    for (int s = 64; s > 0; s >>= 1) {
        if (t < s) red[t] = fmaxf(red[t], red[t + s]);
        __syncthreads();
    }
    float mx = red[0];
    __syncthreads();
    float e = expf(v - mx);
    red[t] = e;
    __syncthreads();
    for (int s = 64; s > 0; s >>= 1) {
        if (t < s) red[t] += red[t + s];
        __syncthreads();
    }
    float inv = 1.f / red[0];
    a[t] = e * inv;
}

__global__ __launch_bounds__(NTH, 1)
void out_kernel(float* __restrict__ out)
{
    extern __shared__ char smem[];
    const int tid = threadIdx.x;
    const int w = tid >> 5;
    const int lane = tid & 31;
    const int wm = (w & 3) * 32;
    const int wn = (w >> 2) * 32;
    const int tile = blockIdx.x;
    const int b = blockIdx.y;
    const int n0 = tile * TN;

    float* ws = (float*)(smem + OSTG) + w * 320;

    // A = softmaxed attn [c][d] hi/lo
    for (int idx = tid; idx < NC * 64; idx += NTH) {
        int dp = idx & 63, c = idx >> 6;
        float2 a2 = *(const float2*)(g_attn + ((size_t)b * NC + c) * NC + 2 * dp);
        u32 lop, hip = split_pair(a2.x, a2.y, lop);
        *(u32*)(smem + OA_HI + c * LDTB + 4 * dp) = hip;
        *(u32*)(smem + OA_LO + c * LDTB + 4 * dp) = lop;
    }
    // B = v tile [n][d] hi/lo (coalesced reads of g_v)
    {
        const float* src = g_v + (size_t)(b * NT + tile) * (TN * NC);
        for (int idx = tid; idx < 64 * TN; idx += NTH) {
            int dp = idx & 63, n = idx >> 6;
            float2 v2 = *(const float2*)(src + (size_t)n * NC + 2 * dp);
            u32 lop, hip = split_pair(v2.x, v2.y, lop);
            *(u32*)(smem + OB_HI + n * LDTB + 4 * dp) = hip;
            *(u32*)(smem + OB_LO + n * LDTB + 4 * dp) = lop;
        }
    }
    __syncthreads();

    FragC acc[2][2];
    float vals[8];

    // out = attn[c][d] x v[d][n] ; A row-major [c][d], B col-major via [n][d]
    gemm_tile((const __nv_bfloat16*)(smem + OA_HI), (const __nv_bfloat16*)(smem + OA_LO),
              (const __nv_bfloat16*)(smem + OB_HI), (const __nv_bfloat16*)(smem + OB_LO),
              wm, wn, acc);

#pragma unroll
    for (int i = 0; i < 2; i++) {
        int c = wm + 16 * i + (lane >> 1);
        float* dst = out + ((size_t)b * NC + c) * NN;
#pragma unroll
        for (int j = 0; j < 2; j++) {
            frag_vals(ws, acc[i][j], lane, vals);
            int nb = wn + 16 * j + (lane & 1) * 8;
#pragma unroll
            for (int t = 0; t < 8; t++) {
                int n = n0 + nb + t;
                if (n < NN) dst[n] = vals[t];
            }
        }
    }
}

extern "C" void kernel_launch(void* const* d_in, const int* in_sizes, int n_in,
                              void* d_out, int out_size)
{
    const float* pc  = (const float*)d_in[0];
    const float* x   = (const float*)d_in[1];
    const float* Wq  = (const float*)d_in[2];
    const float* gq  = (const float*)d_in[3];
    const float* bq  = (const float*)d_in[4];
    const float* mq  = (const float*)d_in[5];
    const float* vq  = (const float*)d_in[6];
    const float* Wk  = (const float*)d_in[7];
    const float* gk  = (const float*)d_in[8];
    const float* bk  = (const float*)d_in[9];
    const float* mk  = (const float*)d_in[10];
    const float* vk  = (const float*)d_in[11];
    const float* Wv  = (const float*)d_in[12];
    const float* gv  = (const float*)d_in[13];
    const float* bv  = (const float*)d_in[14];
    const float* mv  = (const float*)d_in[15];
    const float* vv  = (const float*)d_in[16];
    const float* Wg1 = (const float*)d_in[17];
    const float* bg1 = (const float*)d_in[18];
    const float* Wg2 = (const float*)d_in[19];
    const float* bg2 = (const float*)d_in[20];
    float* out = (float*)d_out;

    cudaFuncSetAttribute(proj_attn_kernel,
                         cudaFuncAttributeMaxDynamicSharedMemorySize, SMEM_A_BYTES);
    cudaFuncSetAttribute(out_kernel,
                         cudaFuncAttributeMaxDynamicSharedMemorySize, SMEM_O_BYTES);

    prep_kernel<<<1, NTH>>>(Wq, Wk, Wv, gq, bq, mq, vq, gk, bk, mk, vk,
                            gv, bv, mv, vv, Wg1, bg1, Wg2, bg2);

    dim3 grid(NT, NB);
    proj_attn_kernel<<<grid, NTH, SMEM_A_BYTES>>>(pc, x);
    softmax_kernel<<<NB * NC, NC>>>();
    out_kernel<<<grid, NTH, SMEM_O_BYTES>>>(out);
}